// round 13
// baseline (speedup 1.0000x reference)
#include <cuda_runtime.h>
#include <cuda_bf16.h>
#include <cuda_fp8.h>
#include <math.h>
#include <stdint.h>

// Problem constants
#define BATCH 1024
#define SEQ   80
#define UNITS 512
#define EMB   100
#define N4    2048
#define ROWS  (SEQ * BATCH)
#define NBLK  128              // persistent grid size (<=148 SMs -> all resident)
#define NTHR  512              // 16 warps
#define QSCALE 16.0f
#define QINV   (1.0f / 256.0f) // undo QSCALE^2 after MMA

// ---------------- static device scratch ----------------
__device__ __nv_bfloat16 g_Xb[(size_t)ROWS * 128];     // gathered embeddings, bf16, padded K=128
__device__ float g_Z1[(size_t)ROWS * N4];              // x@W1 + b1 (reordered cols, fp32)
__device__ __nv_bfloat16 g_W1b[(size_t)N4 * 128];      // W1 reordered, [N][K] bf16, K padded
__device__ float g_b1r[N4];
__device__ float g_b2r[N4];
// fp8 weights (x QSCALE), [N][K] K-major
__device__ uint8_t g_U1q[(size_t)N4 * UNITS];
__device__ uint8_t g_W2q[(size_t)N4 * 2 * UNITS];
// fp8 hidden states (x QSCALE), double buffered
__device__ uint8_t g_h1q[2][(size_t)BATCH * UNITS];
__device__ uint8_t g_h2q[2][(size_t)BATCH * UNITS];
__device__ __nv_bfloat16 g_h2out[(size_t)BATCH * UNITS];  // exact h2 for output projection
__device__ unsigned g_bar_count;
__device__ unsigned g_bar_gen;

__device__ __forceinline__ float tanh_f(float x) {
    float r;
    asm("tanh.approx.f32 %0, %1;" : "=f"(r) : "f"(x));
    return r;
}
__device__ __forceinline__ float sigmoidf_(float x) { return fmaf(0.5f, tanh_f(0.5f * x), 0.5f); }

__device__ __forceinline__ uint8_t f2q(float x) {
    __nv_fp8_e4m3 q(x);
    return *reinterpret_cast<uint8_t*>(&q);
}

__device__ __forceinline__ uint32_t smem_u32(const void* p) {
    uint32_t a;
    asm("{ .reg .u64 t; cvta.to.shared.u64 t, %1; cvt.u32.u64 %0, t; }" : "=r"(a) : "l"(p));
    return a;
}
__device__ __forceinline__ uint32_t sw_off(uint32_t off) {
    return off ^ ((off >> 3) & 0x70);
}
__device__ __forceinline__ void ldmatrix_x4(uint32_t* r, uint32_t addr) {
    asm volatile("ldmatrix.sync.aligned.m8n8.x4.shared.b16 {%0,%1,%2,%3}, [%4];"
                 : "=r"(r[0]), "=r"(r[1]), "=r"(r[2]), "=r"(r[3]) : "r"(addr));
}
__device__ __forceinline__ void mma16816(float* c, const uint32_t* a, const uint32_t* b) {
    asm volatile("mma.sync.aligned.m16n8k16.row.col.f32.bf16.bf16.f32 "
                 "{%0,%1,%2,%3}, {%4,%5,%6,%7}, {%8,%9}, {%0,%1,%2,%3};"
                 : "+f"(c[0]), "+f"(c[1]), "+f"(c[2]), "+f"(c[3])
                 : "r"(a[0]), "r"(a[1]), "r"(a[2]), "r"(a[3]), "r"(b[0]), "r"(b[1]));
}
__device__ __forceinline__ void mma16832q(float* c, const uint32_t* a, const uint32_t* b) {
    asm volatile("mma.sync.aligned.m16n8k32.row.col.f32.e4m3.e4m3.f32 "
                 "{%0,%1,%2,%3}, {%4,%5,%6,%7}, {%8,%9}, {%0,%1,%2,%3};"
                 : "+f"(c[0]), "+f"(c[1]), "+f"(c[2]), "+f"(c[3])
                 : "r"(a[0]), "r"(a[1]), "r"(a[2]), "r"(a[3]), "r"(b[0]), "r"(b[1]));
}
__device__ __forceinline__ void cp_async16(uint32_t dst, const void* src) {
    asm volatile("cp.async.cg.shared.global [%0], [%1], 16;" :: "r"(dst), "l"(src) : "memory");
}
#define CP_COMMIT()   asm volatile("cp.async.commit_group;" ::: "memory")
#define CP_WAIT(n)    asm volatile("cp.async.wait_group %0;" :: "n"(n) : "memory")

// ---------------- reset (per replay; determinism) ----------------
__global__ void reset_kernel() {
    if (threadIdx.x == 0) { g_bar_count = 0; g_bar_gen = 0; }
}

// ---------------- zero states ----------------
__global__ void zero_state_kernel() {
    size_t i = (size_t)blockIdx.x * blockDim.x + threadIdx.x;
    if (i < (size_t)BATCH * UNITS) {
        g_h1q[0][i] = 0; g_h2q[0][i] = 0;
        g_h2out[i] = __float2bfloat16(0.f);
    }
}

// ---------------- prepack: reorder (n = u*4+g); bf16 W1, fp8 U1/[W2;U2] ----------------
__global__ void prepack_kernel(const float* __restrict__ W1, const float* __restrict__ U1,
                               const float* __restrict__ b1, const float* __restrict__ W2,
                               const float* __restrict__ U2, const float* __restrict__ b2) {
    int n = blockIdx.x;
    int u = n >> 2, gg = n & 3;
    int src = gg * UNITS + u;
    for (int k = threadIdx.x; k < 2 * UNITS; k += blockDim.x) {
        float w = (k < UNITS) ? W2[(size_t)k * N4 + src] : U2[(size_t)(k - UNITS) * N4 + src];
        g_W2q[(size_t)n * (2 * UNITS) + k] = f2q(w * QSCALE);
        if (k < UNITS)
            g_U1q[(size_t)n * UNITS + k] = f2q(U1[(size_t)k * N4 + src] * QSCALE);
        if (k < 128)
            g_W1b[(size_t)n * 128 + k] = __float2bfloat16(k < EMB ? W1[(size_t)k * N4 + src] : 0.f);
    }
    if (threadIdx.x == 0) { g_b1r[n] = b1[src]; g_b2r[n] = b2[src]; }
}

// ---------------- embedding gather (bf16, padded to 128 cols) ----------------
__global__ void gather_kernel(const int* __restrict__ tokens, const float* __restrict__ emb) {
    int row = blockIdx.x;
    int t = row / BATCH, b = row - t * BATCH;
    int tok = tokens[(size_t)b * SEQ + t];
    int e = threadIdx.x;
    g_Xb[(size_t)row * 128 + e] = __float2bfloat16(e < EMB ? emb[(size_t)tok * EMB + e] : 0.f);
}

// ================= bf16 mainloop (pregemm only): 128x128 tile, K=128 single chunk =================
#define BSTAGE_BYTES 65536

__device__ __forceinline__ void mma_mainloop_bf16(
    float (&acc)[2][4][4], uint32_t sb,
    const __nv_bfloat16* __restrict__ A0, int astride,
    const __nv_bfloat16* __restrict__ Bw, int bstride, int mo, int no)
{
    int tid = threadIdx.x, wid = tid >> 5, lane = tid & 31;
    int wm = wid >> 2, wn = wid & 3;
    int lr = tid >> 2, lq = (tid & 3) * 2;

    {
        const __nv_bfloat16* ap = A0 + (size_t)(mo + lr) * astride;
        const __nv_bfloat16* bp = Bw + (size_t)(no + lr) * bstride;
#pragma unroll
        for (int sub = 0; sub < 2; sub++) {
#pragma unroll
            for (int q = 0; q < 2; q++) {
                uint32_t off = sw_off((uint32_t)(lr * 128 + (lq + q) * 16)) + (uint32_t)sub * 16384;
                cp_async16(sb + off,         ap + sub * 64 + (lq + q) * 8);
                cp_async16(sb + 32768 + off, bp + sub * 64 + (lq + q) * 8);
            }
        }
        CP_COMMIT();
    }

    uint32_t a_rowoff[2];
#pragma unroll
    for (int mt = 0; mt < 2; mt++)
        a_rowoff[mt] = (uint32_t)((wm * 32 + mt * 16 + (lane & 15)) * 128 + (lane >> 4) * 16);
    uint32_t b_rowoff[2];
#pragma unroll
    for (int pr = 0; pr < 2; pr++)
        b_rowoff[pr] = (uint32_t)((wn * 32 + pr * 16 + ((lane >> 4) & 1) * 8 + (lane & 7)) * 128 + ((lane >> 3) & 1) * 16);

    CP_WAIT(0);
    __syncthreads();

    uint32_t af[2][2][4], bf[2][2][4];
#pragma unroll
    for (int mt = 0; mt < 2; mt++)
        ldmatrix_x4(af[0][mt], sb + sw_off(a_rowoff[mt]));
#pragma unroll
    for (int pr = 0; pr < 2; pr++)
        ldmatrix_x4(bf[0][pr], sb + 32768 + sw_off(b_rowoff[pr]));

#pragma unroll
    for (int ks = 0; ks < 8; ks++) {
        int cb = ks & 1, nb = (ks + 1) & 1;
        if (ks < 7) {
            uint32_t nsub = (uint32_t)((ks + 1) >> 2) * 16384;
            uint32_t nkof = (uint32_t)((ks + 1) & 3) * 32;
#pragma unroll
            for (int mt = 0; mt < 2; mt++)
                ldmatrix_x4(af[nb][mt], sb + nsub + sw_off(a_rowoff[mt] + nkof));
#pragma unroll
            for (int pr = 0; pr < 2; pr++)
                ldmatrix_x4(bf[nb][pr], sb + 32768 + nsub + sw_off(b_rowoff[pr] + nkof));
        }
#pragma unroll
        for (int mt = 0; mt < 2; mt++)
#pragma unroll
            for (int nt = 0; nt < 4; nt++)
                mma16816(acc[mt][nt], af[cb][mt], &bf[cb][nt >> 1][(nt & 1) * 2]);
    }
    __syncthreads();
}

// ---------------- pre-GEMM (bf16 HMMA): Z1 = Xb @ W1b + b1r ----------------
#define SMEM_PRE (1024 + BSTAGE_BYTES)

__global__ __launch_bounds__(NTHR) void pregemm_hmma_kernel() {
    extern __shared__ char dsm[];
    uint32_t raw = smem_u32(dsm);
    uint32_t sb = raw + ((1024u - (raw & 1023u)) & 1023u);

    int lane = threadIdx.x & 31, wid = threadIdx.x >> 5;
    int wm = wid >> 2, wn = wid & 3;
    int mo = blockIdx.y * 128, no = blockIdx.x * 128;

    float acc[2][4][4];
#pragma unroll
    for (int a = 0; a < 2; a++)
#pragma unroll
        for (int b = 0; b < 4; b++)
#pragma unroll
            for (int cc = 0; cc < 4; cc++) acc[a][b][cc] = 0.f;

    mma_mainloop_bf16(acc, sb, g_Xb, 128, g_W1b, 128, mo, no);

#pragma unroll
    for (int mt = 0; mt < 2; mt++)
#pragma unroll
        for (int nt = 0; nt < 4; nt++)
#pragma unroll
            for (int ri = 0; ri < 2; ri++) {
                float v0 = acc[mt][nt][2 * ri + 0];
                float v1 = acc[mt][nt][2 * ri + 1];
                float o0 = __shfl_xor_sync(0xFFFFFFFF, v0, 1);
                float o1 = __shfl_xor_sync(0xFFFFFFFF, v1, 1);
                if ((lane & 1) == 0) {
                    int row_l = wm * 32 + mt * 16 + (lane >> 2) + ri * 8;
                    int c_l = wn * 32 + nt * 8 + (lane & 3) * 2;
                    float4 bb = *(const float4*)(g_b1r + no + c_l);
                    float4 r = make_float4(v0 + bb.x, v1 + bb.y, o0 + bb.z, o1 + bb.w);
                    *(float4*)(g_Z1 + ((size_t)mo + row_l) * N4 + no + c_l) = r;
                }
            }
}

// ================= fp8 mainloop: 128x128 tile, KCQ=128 fp8/chunk, 2-stage =================
// Stage (32KB): A 16K | B 16K (128 rows x 128 bytes each). 4 x k32 steps per chunk.
#define QSTAGE_BYTES 32768

__device__ __forceinline__ void mma_mainloop_fp8(
    float (&acc)[2][4][4], uint32_t sb,
    const uint8_t* __restrict__ A0, const uint8_t* __restrict__ A1, int astride,
    const uint8_t* __restrict__ Bw, int bstride, int mo, int no, int nc)
{
    int tid = threadIdx.x, wid = tid >> 5, lane = tid & 31;
    int wm = wid >> 2, wn = wid & 3;
    int lr = tid >> 2, lq = (tid & 3) * 2;   // 4 threads per 128B row, 2 x 16B lines each

    auto load_chunk = [&](int i, uint32_t stage) {
        int k0 = i * 128;                    // byte == fp8 element
        const uint8_t* asrc = (A1 != nullptr && k0 >= UNITS) ? A1 : A0;
        int kk0 = k0 & (UNITS - 1);
        const uint8_t* ap = asrc + (size_t)(mo + lr) * astride + kk0;
        const uint8_t* bp = Bw + (size_t)(no + lr) * bstride + k0;
#pragma unroll
        for (int q = 0; q < 2; q++) {
            uint32_t off = sw_off((uint32_t)(lr * 128 + (lq + q) * 16));
            cp_async16(stage + off,         ap + (lq + q) * 16);
            cp_async16(stage + 16384 + off, bp + (lq + q) * 16);
        }
        CP_COMMIT();
    };

    uint32_t a_rowoff[2];
#pragma unroll
    for (int mt = 0; mt < 2; mt++)
        a_rowoff[mt] = (uint32_t)((wm * 32 + mt * 16 + (lane & 15)) * 128 + (lane >> 4) * 16);
    uint32_t b_rowoff[2];
#pragma unroll
    for (int pr = 0; pr < 2; pr++)
        b_rowoff[pr] = (uint32_t)((wn * 32 + pr * 16 + ((lane >> 4) & 1) * 8 + (lane & 7)) * 128 + ((lane >> 3) & 1) * 16);

    load_chunk(0, sb);
    CP_WAIT(0);
    __syncthreads();

    for (int i = 0; i < nc; i++) {
        uint32_t cur = sb + (uint32_t)(i & 1) * QSTAGE_BYTES;
        uint32_t nxt = sb + (uint32_t)((i + 1) & 1) * QSTAGE_BYTES;

        if (i + 1 < nc)
            load_chunk(i + 1, nxt);          // gmem->smem overlaps MMA below

        uint32_t af[2][2][4], bf[2][2][4];
#pragma unroll
        for (int mt = 0; mt < 2; mt++)
            ldmatrix_x4(af[0][mt], cur + sw_off(a_rowoff[mt]));
#pragma unroll
        for (int pr = 0; pr < 2; pr++)
            ldmatrix_x4(bf[0][pr], cur + 16384 + sw_off(b_rowoff[pr]));

#pragma unroll
        for (int ks = 0; ks < 4; ks++) {     // 4 x k32 steps, 32-byte stride
            int cb = ks & 1, nb = (ks + 1) & 1;
            if (ks < 3) {
                uint32_t nkof = (uint32_t)(ks + 1) * 32;
#pragma unroll
                for (int mt = 0; mt < 2; mt++)
                    ldmatrix_x4(af[nb][mt], cur + sw_off(a_rowoff[mt] + nkof));
#pragma unroll
                for (int pr = 0; pr < 2; pr++)
                    ldmatrix_x4(bf[nb][pr], cur + 16384 + sw_off(b_rowoff[pr] + nkof));
            }
#pragma unroll
            for (int mt = 0; mt < 2; mt++)
#pragma unroll
                for (int nt = 0; nt < 4; nt++)
                    mma16832q(acc[mt][nt], af[cb][mt], &bf[cb][nt >> 1][(nt & 1) * 2]);
        }

        if (i + 1 < nc) CP_WAIT(0);
        __syncthreads();
    }
}

// ---------------- LSTM gate epilogue (c in SMEM, h -> fp8 [+bf16 for layer2]) ----------------
template <int LAYER>
__device__ __forceinline__ void lstm_epilogue(
    float (&acc)[2][4][4], int t, int mo, int no,
    float* __restrict__ csm, uint8_t* __restrict__ hq)
{
    int lane = threadIdx.x & 31, wid = threadIdx.x >> 5;
    int wm = wid >> 2, wn = wid & 3;
#pragma unroll
    for (int mt = 0; mt < 2; mt++)
#pragma unroll
        for (int nt = 0; nt < 4; nt++)
#pragma unroll
            for (int ri = 0; ri < 2; ri++) {
                float v0 = acc[mt][nt][2 * ri + 0];
                float v1 = acc[mt][nt][2 * ri + 1];
                float o0 = __shfl_xor_sync(0xFFFFFFFF, v0, 1);
                float o1 = __shfl_xor_sync(0xFFFFFFFF, v1, 1);
                if ((lane & 1) == 0) {
                    int row_l = wm * 32 + mt * 16 + (lane >> 2) + ri * 8;
                    int c_l = wn * 32 + nt * 8 + (lane & 3) * 2;
                    const float* zp = (LAYER == 1)
                        ? (g_Z1 + ((size_t)t * BATCH + mo + row_l) * N4 + no + c_l)
                        : (g_b2r + no + c_l);
                    float4 zb = *(const float4*)zp;
                    float zi = fmaf(v0, QINV, zb.x), zf = fmaf(v1, QINV, zb.y);
                    float zg = fmaf(o0, QINV, zb.z), zo = fmaf(o1, QINV, zb.w);
                    float* cp = csm + row_l * 32 + (c_l >> 2);
                    float cn = sigmoidf_(zf) * (*cp) + sigmoidf_(zi) * tanh_f(zg);
                    *cp = cn;
                    float hv = sigmoidf_(zo) * tanh_f(cn);
                    size_t idx = (size_t)(mo + row_l) * UNITS + ((no + c_l) >> 2);
                    hq[idx] = f2q(hv * QSCALE);
                    if (LAYER == 2)
                        g_h2out[idx] = __float2bfloat16(hv);   // exact path for output proj
                }
            }
}

// ---------------- persistent LSTM kernel: all 80 steps, grid barrier ----------------
#define SMEM_PERSIST (1024 + 2 * QSTAGE_BYTES + 2 * 16384)

__device__ __forceinline__ void grid_barrier(unsigned target) {
    __threadfence();
    __syncthreads();
    if (threadIdx.x == 0) {
        unsigned ticket = atomicAdd(&g_bar_count, 1u);
        if (ticket == NBLK - 1) {
            atomicExch(&g_bar_count, 0u);
            __threadfence();
            atomicAdd(&g_bar_gen, 1u);
        } else {
            while (*(volatile unsigned*)&g_bar_gen < target) { }
            __threadfence();
        }
    }
    __syncthreads();
}

__global__ __launch_bounds__(NTHR, 1) void lstm_persist_kernel() {
    extern __shared__ char dsm[];
    uint32_t raw = smem_u32(dsm);
    uint32_t pad = (1024u - (raw & 1023u)) & 1023u;
    uint32_t sb = raw + pad;
    float* c1 = (float*)(dsm + pad + 2 * QSTAGE_BYTES);
    float* c2 = c1 + 4096;

    int tid = threadIdx.x;
    for (int i = tid; i < 4096; i += NTHR) { c1[i] = 0.f; c2[i] = 0.f; }
    __syncthreads();

    int bid = blockIdx.x;
    int mo = (bid >> 4) * 128, no = (bid & 15) * 128;
    unsigned bt = 0;

    for (int t = 0; t < SEQ; t++) {
        // ---- layer 1: z = Z1[t] + h1@U1 ----
        {
            float acc[2][4][4];
#pragma unroll
            for (int a = 0; a < 2; a++)
#pragma unroll
                for (int b = 0; b < 4; b++)
#pragma unroll
                    for (int cc = 0; cc < 4; cc++) acc[a][b][cc] = 0.f;
            if (t > 0)   // t=0: h1 state is zero -> skip GEMM
                mma_mainloop_fp8(acc, sb, g_h1q[t & 1], nullptr, UNITS, g_U1q, UNITS, mo, no, 4);
            lstm_epilogue<1>(acc, t, mo, no, c1, g_h1q[(t + 1) & 1]);
        }
        grid_barrier(++bt);

        // ---- layer 2: z = b2 + [h1_new | h2_old] @ [W2;U2] ----
        {
            float acc[2][4][4];
#pragma unroll
            for (int a = 0; a < 2; a++)
#pragma unroll
                for (int b = 0; b < 4; b++)
#pragma unroll
                    for (int cc = 0; cc < 4; cc++) acc[a][b][cc] = 0.f;
            int nc2 = (t == 0) ? 4 : 8;   // t=0: h2 is zero -> only h1 half
            mma_mainloop_fp8(acc, sb, g_h1q[(t + 1) & 1], g_h2q[t & 1], UNITS, g_W2q, 2 * UNITS, mo, no, nc2);
            lstm_epilogue<2>(acc, t, mo, no, c2, g_h2q[(t + 1) & 1]);
        }
        grid_barrier(++bt);
    }
}

// ---------------- output projection (exact bf16 h2 path) ----------------
__global__ void out_kernel(const float* __restrict__ Wout, const float* __restrict__ bout,
                           float* __restrict__ out) {
    int gw = (blockIdx.x * blockDim.x + threadIdx.x) >> 5;
    int lane = threadIdx.x & 31;
    if (gw >= BATCH) return;
    const __nv_bfloat16* h = g_h2out + (size_t)gw * UNITS;
    float s = 0.f;
    for (int k = lane; k < UNITS; k += 32)
        s += __bfloat162float(h[k]) * Wout[k];
#pragma unroll
    for (int off = 16; off > 0; off >>= 1) s += __shfl_xor_sync(0xFFFFFFFF, s, off);
    if (lane == 0) out[gw] = __fdividef(1.f, 1.f + __expf(-(s + bout[0])));
}

// ---------------- launch ----------------
extern "C" void kernel_launch(void* const* d_in, const int* in_sizes, int n_in,
                              void* d_out, int out_size) {
    const int*   tokens = (const int*)d_in[0];
    const float* emb    = (const float*)d_in[1];
    const float* W1     = (const float*)d_in[2];
    const float* U1     = (const float*)d_in[3];
    const float* b1     = (const float*)d_in[4];
    const float* W2     = (const float*)d_in[5];
    const float* U2     = (const float*)d_in[6];
    const float* b2     = (const float*)d_in[7];
    const float* Wout   = (const float*)d_in[8];
    const float* bout   = (const float*)d_in[9];
    float* out = (float*)d_out;

    cudaFuncSetAttribute(pregemm_hmma_kernel, cudaFuncAttributeMaxDynamicSharedMemorySize, SMEM_PRE);
    cudaFuncSetAttribute(lstm_persist_kernel, cudaFuncAttributeMaxDynamicSharedMemorySize, SMEM_PERSIST);

    reset_kernel<<<1, 32>>>();
    zero_state_kernel<<<(BATCH * UNITS + 255) / 256, 256>>>();
    prepack_kernel<<<N4, 256>>>(W1, U1, b1, W2, U2, b2);
    gather_kernel<<<ROWS, 128>>>(tokens, emb);
    pregemm_hmma_kernel<<<dim3(16, ROWS / 128), NTHR, SMEM_PRE>>>();
    lstm_persist_kernel<<<NBLK, NTHR, SMEM_PERSIST>>>();
    out_kernel<<<(BATCH * 32 + 255) / 256, 256>>>(Wout, bout, out);
}